// round 14
// baseline (speedup 1.0000x reference)
#include <cuda_runtime.h>

// Shapes: x (8,96,256,256) f32. BC=768 channel-slices of 256x256.
// Outputs: xlo (768,128,128) then xhi_dir (768,4,128,128), concatenated in d_out.

#define N_BC   768
#define NPIX   65536           // 256*256
#define NHALF  32768           // 128*256
#define NQ     16384           // 128*128

__device__ float g_xhi[50331648];   // 768*256*256  (also x-hi band)
__device__ float g_s0[25165824];    // 768*128*256  (K1a tmp, then f0-conv even rows)
__device__ float g_s1[25165824];    // 768*128*256  (f1-conv even rows)

// ---------------------------------------------------------------------------
// K1a: row filter (5-tap h, wrap) at even output rows -> tmp (in g_s0)
// tmp[bc,i,w] = sum_u h[u] x[bc,(2i+u-2)&255,w]
// ---------------------------------------------------------------------------
__global__ __launch_bounds__(256) void k1a(const float* __restrict__ x,
                                           const float* __restrict__ hf) {
    int t  = blockIdx.x * 256 + threadIdx.x;     // 6,291,456 threads
    int w4 = t & 63;
    int i  = (t >> 6) & 127;
    int bc = t >> 13;
    float hc[5];
#pragma unroll
    for (int u = 0; u < 5; u++) hc[u] = __ldg(hf + u);
    const float* xb = x + (size_t)bc * NPIX;
    float4 acc = make_float4(0.f, 0.f, 0.f, 0.f);
    int r0 = 2 * i - 2;
#pragma unroll
    for (int u = 0; u < 5; u++) {
        int r = (r0 + u) & 255;
        float4 v = __ldg((const float4*)(xb + r * 256) + w4);
        acc.x += hc[u] * v.x; acc.y += hc[u] * v.y;
        acc.z += hc[u] * v.z; acc.w += hc[u] * v.w;
    }
    ((float4*)(g_s0 + (size_t)bc * NHALF + i * 256))[w4] = acc;
}

// ---------------------------------------------------------------------------
// K1b: column filter at even cols -> xlo (first output block)
// xlo[bc,i,j] = sum_v h[v] tmp[bc,i,(2j+v-2)&255]
// ---------------------------------------------------------------------------
__global__ __launch_bounds__(256) void k1b(const float* __restrict__ hf,
                                           float* __restrict__ out_lo) {
    int t  = blockIdx.x * 256 + threadIdx.x;     // 12,582,912 threads
    int j  = t & 127;
    int i  = (t >> 7) & 127;
    int bc = t >> 14;
    float hc[5];
#pragma unroll
    for (int v = 0; v < 5; v++) hc[v] = __ldg(hf + v);
    const float* tr = g_s0 + (size_t)bc * NHALF + i * 256;
    int c0 = 2 * j - 2;
    float acc = 0.f;
#pragma unroll
    for (int v = 0; v < 5; v++) acc += hc[v] * __ldg(tr + ((c0 + v) & 255));
    out_lo[(size_t)bc * NQ + i * 128 + j] = acc;
}

// ---------------------------------------------------------------------------
// K2: xhi = x - sepfilt(up(xlo), g).  Parity kills half the 7 taps per dim:
// even out-row uses g[1],g[3],g[5]; odd out-row uses g[0],g[2],g[4],g[6].
// Each thread produces a 2x2 output block from a 4x4 xlo patch.
// ---------------------------------------------------------------------------
__global__ __launch_bounds__(256) void k2(const float* __restrict__ x,
                                          const float* __restrict__ gf,
                                          const float* __restrict__ xlo) {
    int t  = blockIdx.x * 256 + threadIdx.x;     // 12,582,912 threads
    int j  = t & 127;
    int i  = (t >> 7) & 127;
    int bc = t >> 14;
    float g0 = __ldg(gf + 0), g1 = __ldg(gf + 1), g2 = __ldg(gf + 2),
          g3 = __ldg(gf + 3), g4 = __ldg(gf + 4), g5 = __ldg(gf + 5),
          g6 = __ldg(gf + 6);
    const float* lo = xlo + (size_t)bc * NQ;
    float X[4][4];
#pragma unroll
    for (int r = 0; r < 4; r++) {
        int rr = (i - 1 + r) & 127;
#pragma unroll
        for (int c = 0; c < 4; c++) {
            int cc = (j - 1 + c) & 127;
            X[r][c] = __ldg(lo + rr * 128 + cc);
        }
    }
    float So[4], Se[4];
#pragma unroll
    for (int r = 0; r < 4; r++) {
        So[r] = g1 * X[r][0] + g3 * X[r][1] + g5 * X[r][2];
        Se[r] = g0 * X[r][0] + g2 * X[r][1] + g4 * X[r][2] + g6 * X[r][3];
    }
    float Gee = g1 * So[0] + g3 * So[1] + g5 * So[2];
    float Geo = g1 * Se[0] + g3 * Se[1] + g5 * Se[2];
    float Goe = g0 * So[0] + g2 * So[1] + g4 * So[2] + g6 * So[3];
    float Goo = g0 * Se[0] + g2 * Se[1] + g4 * Se[2] + g6 * Se[3];

    const float* xb = x + (size_t)bc * NPIX;
    float* hb = g_xhi + (size_t)bc * NPIX;
    float2 xt = __ldg((const float2*)(xb + (2 * i) * 256) + j);
    float2 xu = __ldg((const float2*)(xb + (2 * i + 1) * 256) + j);
    ((float2*)(hb + (2 * i) * 256))[j]     = make_float2(xt.x - Gee, xt.y - Geo);
    ((float2*)(hb + (2 * i + 1) * 256))[j] = make_float2(xu.x - Goe, xu.y - Goo);
}

// ---------------------------------------------------------------------------
// K3: 7x7 wrap conv of xhi at EVEN rows, exploiting f0's support
// (center + 24 odd-parity taps) and f1 = center - odd_sum.
// Tile: 8 output i-rows x full 256 cols; smem holds 21 input rows.
// ---------------------------------------------------------------------------
__global__ __launch_bounds__(256) void k3(const float* __restrict__ f0) {
    __shared__ float xs[21][256];
    __shared__ float fs[49];
    int bid = blockIdx.x;                        // 12288 = 768 * 16
    int ig = bid & 15;
    int bc = bid >> 4;
    int tid = threadIdx.x;
    if (tid < 49) fs[tid] = __ldg(f0 + tid);
    const float* hb = g_xhi + (size_t)bc * NPIX;
    int i0 = ig * 8;
    for (int idx = tid; idx < 21 * 64; idx += 256) {
        int tr = idx >> 6, c4 = idx & 63;
        int r = (2 * i0 - 3 + tr) & 255;
        ((float4*)xs[tr])[c4] = __ldg((const float4*)(hb + r * 256) + c4);
    }
    __syncthreads();

    int tx = tid & 31, ty = tid >> 5;
    int i = i0 + ty;
    float* s0b = g_s0 + (size_t)bc * NHALF + i * 256;
    float* s1b = g_s1 + (size_t)bc * NHALF + i * 256;
    float fc = fs[24];                           // f0[3][3]
#pragma unroll
    for (int dw = 0; dw < 8; dw++) {
        int w = tx + 32 * dw;
        float acc = 0.f;
#pragma unroll
        for (int u = 0; u < 7; u++) {
            const float* row = xs[2 * ty + u];
#pragma unroll
            for (int v = (u & 1) ^ 1; v < 7; v += 2)   // (u+v) odd taps
                acc += fs[u * 7 + v] * row[(w + v - 3) & 255];
        }
        float c = fc * xs[2 * ty + 3][w];
        s0b[w] = c + acc;
        s1b[w] = c - acc;
    }
}

// ---------------------------------------------------------------------------
// K4: direction subbands. sub_{2p+f}[h,j] reads s_p along a sheared
// parallelogram: value = s_p[(h+2j+u-3)&127, (6j+2h+2u+v-9)&255].
// Pre-shear into smem: S[t][c] = s_p[(R0+t)&127, (C0+2t+c)&255],
// tap read = S[a+2b+u][2b+v]  (t=a+2b+u, c=2b+v).  Lanes along a ->
// LDS stride 69 (odd) = conflict-free.  Output staged in smem, written
// coalesced.  f0T output = center+odd, f1T = center-odd.
// ---------------------------------------------------------------------------
#define K4LDC 69
__global__ __launch_bounds__(256) void k4(const float* __restrict__ f0,
                                          float* __restrict__ out_hi) {
    __shared__ float S[100 * K4LDC];
    __shared__ float fts[49];
    __shared__ float Osm[2][32][33];
    int bid = blockIdx.x;                        // 24576 = 2*768*16
    int jg = bid & 3, hg = (bid >> 2) & 3;
    int pbc = bid >> 4;
    int p = (pbc >= 768) ? 1 : 0;
    int bc = pbc - p * 768;
    int tid = threadIdx.x;
    if (tid < 49) {                              // transpose: FT[u][v] = f0[v][u]
        int u = tid / 7, v = tid - u * 7;
        fts[tid] = __ldg(f0 + v * 7 + u);
    }
    int h0 = hg * 32, j0 = jg * 32;
    const float* sp = (p ? g_s1 : g_s0) + (size_t)bc * NHALF;
    int R0 = (h0 + 2 * j0 - 3) & 127;
    int C0 = (6 * j0 + 2 * h0 - 9) & 255;
    for (int idx = tid; idx < 100 * K4LDC; idx += 256) {
        int t = idx / K4LDC;
        int c = idx - t * K4LDC;
        int r = (R0 + t) & 127;
        int col = (C0 + 2 * t + c) & 255;
        S[idx] = __ldg(sp + r * 256 + col);
    }
    __syncthreads();

    int a = tid & 31, bg = tid >> 5;
    float fc = fts[24];
#pragma unroll
    for (int bi = 0; bi < 4; bi++) {
        int b = bg * 4 + bi;
        int rbase = a + 2 * b;
        int cbase = 2 * b;
        float acc = 0.f;
#pragma unroll
        for (int u = 0; u < 7; u++) {
            const float* row = &S[(rbase + u) * K4LDC + cbase];
#pragma unroll
            for (int v = (u & 1) ^ 1; v < 7; v += 2)
                acc += fts[u * 7 + v] * row[v];
        }
        float c = fc * S[(rbase + 3) * K4LDC + cbase + 3];
        Osm[0][a][b] = c + acc;     // f0^T subband
        Osm[1][a][b] = c - acc;     // f1^T subband
    }
    __syncthreads();

    size_t base = (size_t)bc * 4 * NQ;
    for (int k = tid; k < 1024; k += 256) {
        int aa = k >> 5, bb = k & 31;
        size_t pos = (size_t)(h0 + aa) * 128 + (j0 + bb);
        out_hi[base + (size_t)(2 * p + 0) * NQ + pos] = Osm[0][aa][bb];
        out_hi[base + (size_t)(2 * p + 1) * NQ + pos] = Osm[1][aa][bb];
    }
}

// ---------------------------------------------------------------------------
extern "C" void kernel_launch(void* const* d_in, const int* in_sizes, int n_in,
                              void* d_out, int out_size) {
    (void)in_sizes; (void)n_in; (void)out_size;
    const float* x  = (const float*)d_in[0];
    const float* hf = (const float*)d_in[1];
    const float* gf = (const float*)d_in[2];
    const float* f0 = (const float*)d_in[3];
    // d_in[4] (f1) is derived analytically: f1 = f0 * (-1)^(u+v) on support.
    float* out    = (float*)d_out;
    float* out_lo = out;                  // 768*128*128
    float* out_hi = out + 12582912;       // 768*4*128*128

    k1a<<<24576, 256>>>(x, hf);
    k1b<<<49152, 256>>>(hf, out_lo);
    k2 <<<49152, 256>>>(x, gf, out_lo);
    k3 <<<12288, 256>>>(f0);
    k4 <<<24576, 256>>>(f0, out_hi);
}

// round 15
// speedup vs baseline: 1.0120x; 1.0120x over previous
#include <cuda_runtime.h>

// Shapes: x (8,96,256,256) f32. BC=768 channel-slices of 256x256.
// Outputs: xlo (768,128,128) then xhi_dir (768,4,128,128), concatenated in d_out.

#define N_BC   768
#define NPIX   65536           // 256*256
#define NHALF  32768           // 128*256
#define NQ     16384           // 128*128

__device__ float g_xhi[50331648];   // 768*256*256  (also x-hi band)
__device__ float g_s0[25165824];    // 768*128*256  (K1a tmp, then f0-conv even rows)
__device__ float g_s1[25165824];    // 768*128*256  (f1-conv even rows)

// ---------------------------------------------------------------------------
// K1a: row filter (5-tap h, wrap) at even output rows -> tmp (in g_s0)
// tmp[bc,i,w] = sum_u h[u] x[bc,(2i+u-2)&255,w]
// ---------------------------------------------------------------------------
__global__ __launch_bounds__(256) void k1a(const float* __restrict__ x,
                                           const float* __restrict__ hf) {
    int t  = blockIdx.x * 256 + threadIdx.x;     // 6,291,456 threads
    int w4 = t & 63;
    int i  = (t >> 6) & 127;
    int bc = t >> 13;
    float hc[5];
#pragma unroll
    for (int u = 0; u < 5; u++) hc[u] = __ldg(hf + u);
    const float* xb = x + (size_t)bc * NPIX;
    float4 acc = make_float4(0.f, 0.f, 0.f, 0.f);
    int r0 = 2 * i - 2;
#pragma unroll
    for (int u = 0; u < 5; u++) {
        int r = (r0 + u) & 255;
        float4 v = __ldg((const float4*)(xb + r * 256) + w4);
        acc.x += hc[u] * v.x; acc.y += hc[u] * v.y;
        acc.z += hc[u] * v.z; acc.w += hc[u] * v.w;
    }
    ((float4*)(g_s0 + (size_t)bc * NHALF + i * 256))[w4] = acc;
}

// ---------------------------------------------------------------------------
// K1b: column filter at even cols -> xlo (first output block)
// xlo[bc,i,j] = sum_v h[v] tmp[bc,i,(2j+v-2)&255]
// ---------------------------------------------------------------------------
__global__ __launch_bounds__(256) void k1b(const float* __restrict__ hf,
                                           float* __restrict__ out_lo) {
    int t  = blockIdx.x * 256 + threadIdx.x;     // 12,582,912 threads
    int j  = t & 127;
    int i  = (t >> 7) & 127;
    int bc = t >> 14;
    float hc[5];
#pragma unroll
    for (int v = 0; v < 5; v++) hc[v] = __ldg(hf + v);
    const float* tr = g_s0 + (size_t)bc * NHALF + i * 256;
    int c0 = 2 * j - 2;
    float acc = 0.f;
#pragma unroll
    for (int v = 0; v < 5; v++) acc += hc[v] * __ldg(tr + ((c0 + v) & 255));
    out_lo[(size_t)bc * NQ + i * 128 + j] = acc;
}

// ---------------------------------------------------------------------------
// K2: xhi = x - sepfilt(up(xlo), g).  Parity kills half the 7 taps per dim:
// even out-row uses g[1],g[3],g[5]; odd out-row uses g[0],g[2],g[4],g[6].
// Each thread produces a 2x2 output block from a 4x4 xlo patch.
// ---------------------------------------------------------------------------
__global__ __launch_bounds__(256) void k2(const float* __restrict__ x,
                                          const float* __restrict__ gf,
                                          const float* __restrict__ xlo) {
    int t  = blockIdx.x * 256 + threadIdx.x;     // 12,582,912 threads
    int j  = t & 127;
    int i  = (t >> 7) & 127;
    int bc = t >> 14;
    float g0 = __ldg(gf + 0), g1 = __ldg(gf + 1), g2 = __ldg(gf + 2),
          g3 = __ldg(gf + 3), g4 = __ldg(gf + 4), g5 = __ldg(gf + 5),
          g6 = __ldg(gf + 6);
    const float* lo = xlo + (size_t)bc * NQ;
    float X[4][4];
#pragma unroll
    for (int r = 0; r < 4; r++) {
        int rr = (i - 1 + r) & 127;
#pragma unroll
        for (int c = 0; c < 4; c++) {
            int cc = (j - 1 + c) & 127;
            X[r][c] = __ldg(lo + rr * 128 + cc);
        }
    }
    float So[4], Se[4];
#pragma unroll
    for (int r = 0; r < 4; r++) {
        So[r] = g1 * X[r][0] + g3 * X[r][1] + g5 * X[r][2];
        Se[r] = g0 * X[r][0] + g2 * X[r][1] + g4 * X[r][2] + g6 * X[r][3];
    }
    float Gee = g1 * So[0] + g3 * So[1] + g5 * So[2];
    float Geo = g1 * Se[0] + g3 * Se[1] + g5 * Se[2];
    float Goe = g0 * So[0] + g2 * So[1] + g4 * So[2] + g6 * So[3];
    float Goo = g0 * Se[0] + g2 * Se[1] + g4 * Se[2] + g6 * Se[3];

    const float* xb = x + (size_t)bc * NPIX;
    float* hb = g_xhi + (size_t)bc * NPIX;
    float2 xt = __ldg((const float2*)(xb + (2 * i) * 256) + j);
    float2 xu = __ldg((const float2*)(xb + (2 * i + 1) * 256) + j);
    ((float2*)(hb + (2 * i) * 256))[j]     = make_float2(xt.x - Gee, xt.y - Geo);
    ((float2*)(hb + (2 * i + 1) * 256))[j] = make_float2(xu.x - Goe, xu.y - Goo);
}

// ---------------------------------------------------------------------------
// K3: 7x7 wrap conv of xhi at EVEN rows, exploiting f0's support
// (center + 24 odd-parity taps) and f1 = center - odd_sum.
// Tile: 8 output i-rows x full 256 cols; smem holds 21 input rows.
// ---------------------------------------------------------------------------
__global__ __launch_bounds__(256) void k3(const float* __restrict__ f0) {
    __shared__ float xs[21][256];
    __shared__ float fs[49];
    int bid = blockIdx.x;                        // 12288 = 768 * 16
    int ig = bid & 15;
    int bc = bid >> 4;
    int tid = threadIdx.x;
    if (tid < 49) fs[tid] = __ldg(f0 + tid);
    const float* hb = g_xhi + (size_t)bc * NPIX;
    int i0 = ig * 8;
    for (int idx = tid; idx < 21 * 64; idx += 256) {
        int tr = idx >> 6, c4 = idx & 63;
        int r = (2 * i0 - 3 + tr) & 255;
        ((float4*)xs[tr])[c4] = __ldg((const float4*)(hb + r * 256) + c4);
    }
    __syncthreads();

    int tx = tid & 31, ty = tid >> 5;
    int i = i0 + ty;
    float* s0b = g_s0 + (size_t)bc * NHALF + i * 256;
    float* s1b = g_s1 + (size_t)bc * NHALF + i * 256;
    float fc = fs[24];                           // f0[3][3]
#pragma unroll
    for (int dw = 0; dw < 8; dw++) {
        int w = tx + 32 * dw;
        float acc = 0.f;
#pragma unroll
        for (int u = 0; u < 7; u++) {
            const float* row = xs[2 * ty + u];
#pragma unroll
            for (int v = (u & 1) ^ 1; v < 7; v += 2)   // (u+v) odd taps
                acc += fs[u * 7 + v] * row[(w + v - 3) & 255];
        }
        float c = fc * xs[2 * ty + 3][w];
        s0b[w] = c + acc;
        s1b[w] = c - acc;
    }
}

// ---------------------------------------------------------------------------
// K4: direction subbands. sub_{2p+f}[h,j] reads s_p along a sheared
// parallelogram: value = s_p[(h+2j+u-3)&127, (6j+2h+2u+v-9)&255].
// Pre-shear into smem: S[t][c] = s_p[(R0+t)&127, (C0+2t+c)&255],
// tap read = S[a+2b+u][2b+v]  (t=a+2b+u, c=2b+v).  Lanes along a ->
// LDS stride 69 (odd) = conflict-free.  Output staged in smem, written
// coalesced.  f0T output = center+odd, f1T = center-odd.
// ---------------------------------------------------------------------------
#define K4LDC 69
__global__ __launch_bounds__(256) void k4(const float* __restrict__ f0,
                                          float* __restrict__ out_hi) {
    __shared__ float S[100 * K4LDC];
    __shared__ float fts[49];
    __shared__ float Osm[2][32][33];
    int bid = blockIdx.x;                        // 24576 = 2*768*16
    int jg = bid & 3, hg = (bid >> 2) & 3;
    int pbc = bid >> 4;
    int p = (pbc >= 768) ? 1 : 0;
    int bc = pbc - p * 768;
    int tid = threadIdx.x;
    if (tid < 49) {                              // transpose: FT[u][v] = f0[v][u]
        int u = tid / 7, v = tid - u * 7;
        fts[tid] = __ldg(f0 + v * 7 + u);
    }
    int h0 = hg * 32, j0 = jg * 32;
    const float* sp = (p ? g_s1 : g_s0) + (size_t)bc * NHALF;
    int R0 = (h0 + 2 * j0 - 3) & 127;
    int C0 = (6 * j0 + 2 * h0 - 9) & 255;
    for (int idx = tid; idx < 100 * K4LDC; idx += 256) {
        int t = idx / K4LDC;
        int c = idx - t * K4LDC;
        int r = (R0 + t) & 127;
        int col = (C0 + 2 * t + c) & 255;
        S[idx] = __ldg(sp + r * 256 + col);
    }
    __syncthreads();

    int a = tid & 31, bg = tid >> 5;
    float fc = fts[24];
#pragma unroll
    for (int bi = 0; bi < 4; bi++) {
        int b = bg * 4 + bi;
        int rbase = a + 2 * b;
        int cbase = 2 * b;
        float acc = 0.f;
#pragma unroll
        for (int u = 0; u < 7; u++) {
            const float* row = &S[(rbase + u) * K4LDC + cbase];
#pragma unroll
            for (int v = (u & 1) ^ 1; v < 7; v += 2)
                acc += fts[u * 7 + v] * row[v];
        }
        float c = fc * S[(rbase + 3) * K4LDC + cbase + 3];
        Osm[0][a][b] = c + acc;     // f0^T subband
        Osm[1][a][b] = c - acc;     // f1^T subband
    }
    __syncthreads();

    size_t base = (size_t)bc * 4 * NQ;
    for (int k = tid; k < 1024; k += 256) {
        int aa = k >> 5, bb = k & 31;
        size_t pos = (size_t)(h0 + aa) * 128 + (j0 + bb);
        out_hi[base + (size_t)(2 * p + 0) * NQ + pos] = Osm[0][aa][bb];
        out_hi[base + (size_t)(2 * p + 1) * NQ + pos] = Osm[1][aa][bb];
    }
}

// ---------------------------------------------------------------------------
extern "C" void kernel_launch(void* const* d_in, const int* in_sizes, int n_in,
                              void* d_out, int out_size) {
    (void)in_sizes; (void)n_in; (void)out_size;
    const float* x  = (const float*)d_in[0];
    const float* hf = (const float*)d_in[1];
    const float* gf = (const float*)d_in[2];
    const float* f0 = (const float*)d_in[3];
    // d_in[4] (f1) is derived analytically: f1 = f0 * (-1)^(u+v) on support.
    float* out    = (float*)d_out;
    float* out_lo = out;                  // 768*128*128
    float* out_hi = out + 12582912;       // 768*4*128*128

    k1a<<<24576, 256>>>(x, hf);
    k1b<<<49152, 256>>>(hf, out_lo);
    k2 <<<49152, 256>>>(x, gf, out_lo);
    k3 <<<12288, 256>>>(f0);
    k4 <<<24576, 256>>>(f0, out_hi);
}